// round 1
// baseline (speedup 1.0000x reference)
#include <cuda_runtime.h>
#include <cuda_bf16.h>
#include <math.h>

#define EMB 512
#define S_LEN 2048
#define NBATCH 4
#define NHEADS 8
#define HDIM 64
#define BR 64
#define BC 64

// Scratch (allocation-free rule: device globals). 16 MB each.
__device__ float g_K[NBATCH * S_LEN * EMB];
__device__ float g_V[NBATCH * S_LEN * EMB];
__device__ float g_C[NBATCH * S_LEN * EMB];

// ---------------------------------------------------------------------------
// GEMM: C[M, 512] = A[M, 512] @ W[512, 512]^T (+ optional bias)
// 128x128 tile, BK=8, 256 threads, 8x8 register microtile.
// ---------------------------------------------------------------------------
__global__ __launch_bounds__(256) void gemm_nt(
    const float* __restrict__ A, const float* __restrict__ W,
    const float* __restrict__ bias, float* __restrict__ C, int M)
{
    __shared__ float As[8][132];  // padded: conflict-free transposed stores
    __shared__ float Bs[8][132];

    const int bm = blockIdx.x * 128;
    const int bn = blockIdx.y * 128;
    const int tid = threadIdx.x;
    const int tx = tid & 15;     // 0..15 -> cols
    const int ty = tid >> 4;     // 0..15 -> rows

    const int lrow = tid >> 1;          // 0..127
    const int lk4  = (tid & 1) * 4;     // 0 or 4

    const float* Ap = A + (size_t)(bm + lrow) * EMB + lk4;
    const float* Wp = W + (size_t)(bn + lrow) * EMB + lk4;

    float acc[8][8];
    #pragma unroll
    for (int i = 0; i < 8; i++)
        #pragma unroll
        for (int j = 0; j < 8; j++) acc[i][j] = 0.f;

    for (int k0 = 0; k0 < EMB; k0 += 8) {
        float4 av = *(const float4*)(Ap + k0);
        float4 wv = *(const float4*)(Wp + k0);
        __syncthreads();
        As[lk4 + 0][lrow] = av.x;
        As[lk4 + 1][lrow] = av.y;
        As[lk4 + 2][lrow] = av.z;
        As[lk4 + 3][lrow] = av.w;
        Bs[lk4 + 0][lrow] = wv.x;
        Bs[lk4 + 1][lrow] = wv.y;
        Bs[lk4 + 2][lrow] = wv.z;
        Bs[lk4 + 3][lrow] = wv.w;
        __syncthreads();

        #pragma unroll
        for (int kk = 0; kk < 8; kk++) {
            float a[8], b[8];
            float4 a0 = *(const float4*)&As[kk][ty * 8];
            float4 a1 = *(const float4*)&As[kk][ty * 8 + 4];
            float4 b0 = *(const float4*)&Bs[kk][tx * 8];
            float4 b1 = *(const float4*)&Bs[kk][tx * 8 + 4];
            a[0]=a0.x; a[1]=a0.y; a[2]=a0.z; a[3]=a0.w;
            a[4]=a1.x; a[5]=a1.y; a[6]=a1.z; a[7]=a1.w;
            b[0]=b0.x; b[1]=b0.y; b[2]=b0.z; b[3]=b0.w;
            b[4]=b1.x; b[5]=b1.y; b[6]=b1.z; b[7]=b1.w;
            #pragma unroll
            for (int i = 0; i < 8; i++)
                #pragma unroll
                for (int j = 0; j < 8; j++)
                    acc[i][j] = fmaf(a[i], b[j], acc[i][j]);
        }
    }

    float bb[8];
    #pragma unroll
    for (int j = 0; j < 8; j++) bb[j] = bias ? bias[bn + tx * 8 + j] : 0.f;

    #pragma unroll
    for (int i = 0; i < 8; i++) {
        float* crow = C + (size_t)(bm + ty * 8 + i) * EMB + bn + tx * 8;
        float4 c0 = make_float4(acc[i][0] + bb[0], acc[i][1] + bb[1],
                                acc[i][2] + bb[2], acc[i][3] + bb[3]);
        float4 c1 = make_float4(acc[i][4] + bb[4], acc[i][5] + bb[5],
                                acc[i][6] + bb[6], acc[i][7] + bb[7]);
        *(float4*)(crow + 0) = c0;
        *(float4*)(crow + 4) = c1;
    }
}

// ---------------------------------------------------------------------------
// Flash attention: one CTA per (n, qtile, h). 256 threads.
// Thread t -> q row r = t/4, lane-in-row lr = t%4.
//   score phase : 16 cols (c = lr + 4*jj), f4-vectorized over D
//   PV phase    : 16 output dims (d = lr*16 .. +15)
// Q/K smem XOR-swizzled at float4 granularity for conflict-free broadcasts.
// Mask tile (stride 65) and P tile share the same smem (per-cell same owner).
// ---------------------------------------------------------------------------
__global__ __launch_bounds__(256) void attn_kernel(
    const float* __restrict__ Q,     // raw query [N, S, 512]
    const int*   __restrict__ mask,  // [N, 1, S, S]
    const float* __restrict__ Kproj, // g_K
    const float* __restrict__ Vproj, // g_V
    float* __restrict__ ctx)         // g_C
{
    extern __shared__ float sm[];
    float* Qs = sm;               // 64*64
    float* Ks = sm + 4096;        // 64*64 (swizzled)
    float* Vs = sm + 8192;        // 64*64 (plain)
    float* Ps = sm + 12288;       // 64*65 (also mask tile, as int)
    int*   Ms = (int*)Ps;

    const int bx = blockIdx.x;
    const int h  = bx % NHEADS;
    const int qt = (bx / NHEADS) % (S_LEN / BR);
    const int n  = bx / (NHEADS * (S_LEN / BR));

    const int tid = threadIdx.x;
    const int r   = tid >> 2;   // q row within tile
    const int lr  = tid & 3;

    const int lrow = tid >> 4;  // loader row (step 16)
    const int lc4  = tid & 15;  // loader float4 col

    // Load Q tile (swizzle by (row>>1)&3)
    for (int rr = lrow; rr < BR; rr += 16) {
        float4 v = *(const float4*)(Q + ((size_t)(n * S_LEN + qt * BR + rr)) * EMB
                                      + h * HDIM + lc4 * 4);
        *(float4*)(Qs + rr * 64 + ((lc4 ^ ((rr >> 1) & 3)) << 2)) = v;
    }

    float m_i = -1e30f, l_i = 0.f;
    float acc[16];
    #pragma unroll
    for (int i = 0; i < 16; i++) acc[i] = 0.f;

    const float scale = 0.044194173824159216f;  // 1/sqrt(512)
    const int qsw = (r >> 1) & 3;

    for (int kt = 0; kt < S_LEN / BC; kt++) {
        __syncthreads();  // previous PV done

        // Load K (swizzled by row&3), V (plain), mask (stride 65)
        for (int rr = lrow; rr < BC; rr += 16) {
            size_t grow = (size_t)(n * S_LEN + kt * BC + rr) * EMB + h * HDIM;
            float4 kv = *(const float4*)(Kproj + grow + lc4 * 4);
            float4 vv = *(const float4*)(Vproj + grow + lc4 * 4);
            *(float4*)(Ks + rr * 64 + ((lc4 ^ (rr & 3)) << 2)) = kv;
            *(float4*)(Vs + rr * 64 + lc4 * 4) = vv;
            const int* mrow = mask + ((size_t)n * S_LEN + qt * BR + rr) * S_LEN
                                   + kt * BC + lc4 * 4;
            int4 mv = *(const int4*)mrow;
            Ms[rr * 65 + lc4 * 4 + 0] = mv.x;
            Ms[rr * 65 + lc4 * 4 + 1] = mv.y;
            Ms[rr * 65 + lc4 * 4 + 2] = mv.z;
            Ms[rr * 65 + lc4 * 4 + 3] = mv.w;
        }
        __syncthreads();

        // Scores: s[jj] = Q[r,:] . K[lr+4jj,:]
        float s[16];
        #pragma unroll
        for (int jj = 0; jj < 16; jj++) s[jj] = 0.f;

        #pragma unroll 4
        for (int d4 = 0; d4 < 16; d4++) {
            float4 qv = *(const float4*)(Qs + r * 64 + ((d4 ^ qsw) << 2));
            #pragma unroll
            for (int jj = 0; jj < 16; jj++) {
                int c = lr + 4 * jj;
                float4 kv = *(const float4*)(Ks + c * 64 + ((d4 ^ lr) << 2));
                s[jj] = fmaf(qv.x, kv.x, s[jj]);
                s[jj] = fmaf(qv.y, kv.y, s[jj]);
                s[jj] = fmaf(qv.z, kv.z, s[jj]);
                s[jj] = fmaf(qv.w, kv.w, s[jj]);
            }
        }

        // Mask + scale
        #pragma unroll
        for (int jj = 0; jj < 16; jj++) {
            int mv = Ms[r * 65 + lr + 4 * jj];
            s[jj] = mv ? s[jj] * scale : -1e30f;
        }

        // Online softmax
        float tm = s[0];
        #pragma unroll
        for (int jj = 1; jj < 16; jj++) tm = fmaxf(tm, s[jj]);
        tm = fmaxf(tm, __shfl_xor_sync(0xffffffffu, tm, 1));
        tm = fmaxf(tm, __shfl_xor_sync(0xffffffffu, tm, 2));
        float m_new = fmaxf(m_i, tm);
        float corr = __expf(m_i - m_new);

        float psum = 0.f;
        #pragma unroll
        for (int jj = 0; jj < 16; jj++) {
            float p = __expf(s[jj] - m_new);
            if (s[jj] < -1e29f) p = 0.f;
            Ps[r * 65 + lr + 4 * jj] = p;
            psum += p;
        }
        psum += __shfl_xor_sync(0xffffffffu, psum, 1);
        psum += __shfl_xor_sync(0xffffffffu, psum, 2);
        l_i = l_i * corr + psum;
        m_i = m_new;
        #pragma unroll
        for (int i = 0; i < 16; i++) acc[i] *= corr;

        __syncthreads();  // all P written before PV

        // PV: acc[d] += sum_c P[r][c] * V[c][lr*16 + d]
        #pragma unroll 4
        for (int c = 0; c < BC; c++) {
            float p = Ps[r * 65 + c];
            const float* vrow = Vs + c * 64 + lr * 16;
            float4 v0 = *(const float4*)(vrow + 0);
            float4 v1 = *(const float4*)(vrow + 4);
            float4 v2 = *(const float4*)(vrow + 8);
            float4 v3 = *(const float4*)(vrow + 12);
            acc[0]  = fmaf(p, v0.x, acc[0]);
            acc[1]  = fmaf(p, v0.y, acc[1]);
            acc[2]  = fmaf(p, v0.z, acc[2]);
            acc[3]  = fmaf(p, v0.w, acc[3]);
            acc[4]  = fmaf(p, v1.x, acc[4]);
            acc[5]  = fmaf(p, v1.y, acc[5]);
            acc[6]  = fmaf(p, v1.z, acc[6]);
            acc[7]  = fmaf(p, v1.w, acc[7]);
            acc[8]  = fmaf(p, v2.x, acc[8]);
            acc[9]  = fmaf(p, v2.y, acc[9]);
            acc[10] = fmaf(p, v2.z, acc[10]);
            acc[11] = fmaf(p, v2.w, acc[11]);
            acc[12] = fmaf(p, v3.x, acc[12]);
            acc[13] = fmaf(p, v3.y, acc[13]);
            acc[14] = fmaf(p, v3.z, acc[14]);
            acc[15] = fmaf(p, v3.w, acc[15]);
        }
    }

    // Normalize + write ctx[n, qt*64+r, h*64 + lr*16 .. +15]
    float inv = 1.f / l_i;
    float* orow = ctx + (size_t)(n * S_LEN + qt * BR + r) * EMB + h * HDIM + lr * 16;
    #pragma unroll
    for (int ii = 0; ii < 4; ii++) {
        float4 o = make_float4(acc[ii * 4 + 0] * inv, acc[ii * 4 + 1] * inv,
                               acc[ii * 4 + 2] * inv, acc[ii * 4 + 3] * inv);
        *(float4*)(orow + ii * 4) = o;
    }
}

// ---------------------------------------------------------------------------

extern "C" void kernel_launch(void* const* d_in, const int* in_sizes, int n_in,
                              void* d_out, int out_size)
{
    const float* values = (const float*)d_in[0];
    const float* keys_  = (const float*)d_in[1];
    const float* query  = (const float*)d_in[2];
    const int*   mask   = (const int*)d_in[3];
    // d_in[4] = Wq : intentionally unused (reference discards q_proj)
    const float* Wk = (const float*)d_in[5];
    const float* Wv = (const float*)d_in[6];
    const float* Wo = (const float*)d_in[7];
    const float* bo = (const float*)d_in[8];
    float* out = (float*)d_out;

    float *Kp, *Vp, *Cp;
    cudaGetSymbolAddress((void**)&Kp, g_K);
    cudaGetSymbolAddress((void**)&Vp, g_V);
    cudaGetSymbolAddress((void**)&Cp, g_C);

    const int M = NBATCH * S_LEN;  // 8192
    dim3 ggrid(M / 128, EMB / 128);

    // K = keys @ Wk^T ; V = values @ Wv^T
    gemm_nt<<<ggrid, 256>>>(keys_, Wk, nullptr, Kp, M);
    gemm_nt<<<ggrid, 256>>>(values, Wv, nullptr, Vp, M);

    // Attention (raw query — bug-faithful)
    const int smem_bytes = (4096 * 3 + 64 * 65) * 4;  // 65792
    cudaFuncSetAttribute(attn_kernel, cudaFuncAttributeMaxDynamicSharedMemorySize,
                         smem_bytes);
    int nblocks = NBATCH * (S_LEN / BR) * NHEADS;  // 1024, h fastest for mask L2 reuse
    attn_kernel<<<nblocks, 256, smem_bytes>>>(query, mask, Kp, Vp, Cp);

    // out = ctx @ Wo^T + bo
    gemm_nt<<<ggrid, 256>>>(Cp, Wo, bo, out, M);
}

// round 10
// speedup vs baseline: 4.6676x; 4.6676x over previous
#include <cuda_runtime.h>
#include <cuda_bf16.h>
#include <math.h>
#include <stdint.h>

#define EMB 512
#define S_LEN 2048
#define NBATCH 4
#define NHEADS 8
#define HDIM 64
#define BCK 64            // keys per tile

// Scratch (allocation-free rule: device globals). 16 MB each.
__device__ float g_K[NBATCH * S_LEN * EMB];
__device__ float g_V[NBATCH * S_LEN * EMB];
__device__ float g_C[NBATCH * S_LEN * EMB];

// ---------------------------------------------------------------------------
// fp32 GEMM: C[M, 512] = A[M, 512] @ W[512, 512]^T (+ optional bias)
// (measured at fp32 roofline in round 1)
// ---------------------------------------------------------------------------
__global__ __launch_bounds__(256) void gemm_nt(
    const float* __restrict__ A, const float* __restrict__ W,
    const float* __restrict__ bias, float* __restrict__ C, int M)
{
    __shared__ float As[8][132];
    __shared__ float Bs[8][132];

    const int bm = blockIdx.x * 128;
    const int bn = blockIdx.y * 128;
    const int tid = threadIdx.x;
    const int tx = tid & 15;
    const int ty = tid >> 4;

    const int lrow = tid >> 1;
    const int lk4  = (tid & 1) * 4;

    const float* Ap = A + (size_t)(bm + lrow) * EMB + lk4;
    const float* Wp = W + (size_t)(bn + lrow) * EMB + lk4;

    float acc[8][8];
    #pragma unroll
    for (int i = 0; i < 8; i++)
        #pragma unroll
        for (int j = 0; j < 8; j++) acc[i][j] = 0.f;

    for (int k0 = 0; k0 < EMB; k0 += 8) {
        float4 av = *(const float4*)(Ap + k0);
        float4 wv = *(const float4*)(Wp + k0);
        __syncthreads();
        As[lk4 + 0][lrow] = av.x;
        As[lk4 + 1][lrow] = av.y;
        As[lk4 + 2][lrow] = av.z;
        As[lk4 + 3][lrow] = av.w;
        Bs[lk4 + 0][lrow] = wv.x;
        Bs[lk4 + 1][lrow] = wv.y;
        Bs[lk4 + 2][lrow] = wv.z;
        Bs[lk4 + 3][lrow] = wv.w;
        __syncthreads();

        #pragma unroll
        for (int kk = 0; kk < 8; kk++) {
            float a[8], b[8];
            float4 a0 = *(const float4*)&As[kk][ty * 8];
            float4 a1 = *(const float4*)&As[kk][ty * 8 + 4];
            float4 b0 = *(const float4*)&Bs[kk][tx * 8];
            float4 b1 = *(const float4*)&Bs[kk][tx * 8 + 4];
            a[0]=a0.x; a[1]=a0.y; a[2]=a0.z; a[3]=a0.w;
            a[4]=a1.x; a[5]=a1.y; a[6]=a1.z; a[7]=a1.w;
            b[0]=b0.x; b[1]=b0.y; b[2]=b0.z; b[3]=b0.w;
            b[4]=b1.x; b[5]=b1.y; b[6]=b1.z; b[7]=b1.w;
            #pragma unroll
            for (int i = 0; i < 8; i++)
                #pragma unroll
                for (int j = 0; j < 8; j++)
                    acc[i][j] = fmaf(a[i], b[j], acc[i][j]);
        }
    }

    float bb[8];
    #pragma unroll
    for (int j = 0; j < 8; j++) bb[j] = bias ? bias[bn + tx * 8 + j] : 0.f;

    #pragma unroll
    for (int i = 0; i < 8; i++) {
        float* crow = C + (size_t)(bm + ty * 8 + i) * EMB + bn + tx * 8;
        float4 c0 = make_float4(acc[i][0] + bb[0], acc[i][1] + bb[1],
                                acc[i][2] + bb[2], acc[i][3] + bb[3]);
        float4 c1 = make_float4(acc[i][4] + bb[4], acc[i][5] + bb[5],
                                acc[i][6] + bb[6], acc[i][7] + bb[7]);
        *(float4*)(crow + 0) = c0;
        *(float4*)(crow + 4) = c1;
    }
}

// ---------------------------------------------------------------------------
// mma.sync flash attention. CTA = (n, qt, h): 128 q-rows, 8 warps x 16 rows,
// 32 k-tiles of 64 keys. Split bf16 (3 products / GEMM), no-max softmax.
// SMEM: each split tile has its full rows x 128B footprint (disjoint map).
// ---------------------------------------------------------------------------
#define SM_QH  0          // 128 x 128B = 16384
#define SM_QL  16384      // 16384
#define SM_KH  32768      // 64 x 128B = 8192
#define SM_KL  40960      // 8192
#define SM_VH  49152      // 8192
#define SM_VL  57344      // 8192
#define SM_MSK 65536      // 128 rows x 72B mask bytes
#define SM_TOTAL 74752    // -> 2 CTAs/SM

__device__ __forceinline__ uint32_t smem_u32(const void* p) {
    uint32_t a;
    asm("{ .reg .u64 t; cvta.to.shared.u64 t, %1; cvt.u32.u64 %0, t; }"
        : "=r"(a) : "l"(p));
    return a;
}

__device__ __forceinline__ void ldsm4(uint32_t* r, uint32_t addr) {
    asm volatile("ldmatrix.sync.aligned.m8n8.x4.shared.b16 {%0,%1,%2,%3}, [%4];"
                 : "=r"(r[0]), "=r"(r[1]), "=r"(r[2]), "=r"(r[3]) : "r"(addr));
}

__device__ __forceinline__ void ldsm4t(uint32_t* r, uint32_t addr) {
    asm volatile("ldmatrix.sync.aligned.m8n8.x4.trans.shared.b16 {%0,%1,%2,%3}, [%4];"
                 : "=r"(r[0]), "=r"(r[1]), "=r"(r[2]), "=r"(r[3]) : "r"(addr));
}

__device__ __forceinline__ void mma16816(float* d, const uint32_t* a,
                                         const uint32_t* b) {
    asm volatile(
        "mma.sync.aligned.m16n8k16.row.col.f32.bf16.bf16.f32 "
        "{%0,%1,%2,%3}, {%4,%5,%6,%7}, {%8,%9}, {%0,%1,%2,%3};"
        : "+f"(d[0]), "+f"(d[1]), "+f"(d[2]), "+f"(d[3])
        : "r"(a[0]), "r"(a[1]), "r"(a[2]), "r"(a[3]), "r"(b[0]), "r"(b[1]));
}

__device__ __forceinline__ uint32_t packbf2(float a, float b) {
    __nv_bfloat162 t = __floats2bfloat162_rn(a, b);   // .x=a (low), .y=b (high)
    return *(uint32_t*)&t;
}

// Load ROWS x 64 fp32 tile (row stride EMB), split hi/lo bf16, store to
// 128B rows with XOR-swizzled 16B chunks: off = row*128 + ((c ^ (row&7))<<4).
template <int ROWS>
__device__ __forceinline__ void load_split_tile(const float* base, char* dh,
                                                char* dl, int tid) {
    #pragma unroll
    for (int i = 0; i < ROWS / 32; i++) {
        int g = tid + (i << 8);          // ROWS rows x 8 chunks
        int rr = g >> 3, g8 = g & 7;
        const float* s = base + (size_t)rr * EMB + g8 * 8;
        float4 f0 = *(const float4*)s;
        float4 f1 = *(const float4*)(s + 4);
        float vs[8] = {f0.x, f0.y, f0.z, f0.w, f1.x, f1.y, f1.z, f1.w};
        uint32_t uh[4], ul[4];
        #pragma unroll
        for (int j = 0; j < 4; j++) {
            float a = vs[2 * j], b = vs[2 * j + 1];
            float ar = a - __bfloat162float(__float2bfloat16_rn(a));
            float br = b - __bfloat162float(__float2bfloat16_rn(b));
            uh[j] = packbf2(a, b);
            ul[j] = packbf2(ar, br);
        }
        uint32_t off = (uint32_t)(rr * 128) + (((uint32_t)g8 ^ ((uint32_t)rr & 7)) << 4);
        *(uint4*)(dh + off) = make_uint4(uh[0], uh[1], uh[2], uh[3]);
        *(uint4*)(dl + off) = make_uint4(ul[0], ul[1], ul[2], ul[3]);
    }
}

__global__ __launch_bounds__(256, 2) void attn3(
    const float* __restrict__ Q, const int* __restrict__ mask,
    const float* __restrict__ Kp, const float* __restrict__ Vp,
    float* __restrict__ ctx)
{
    extern __shared__ __align__(16) char sm[];
    const uint32_t smb = smem_u32(sm);
    const int tid  = threadIdx.x;
    const int wid  = tid >> 5;
    const int lane = tid & 31;
    const int g    = lane >> 3;
    const int lr   = lane & 7;
    const int qb   = wid << 4;           // warp's q-row base (16 rows)

    const int bx = blockIdx.x;
    const int h  = bx & 7;
    const int qt = (bx >> 3) & 15;
    const int n  = bx >> 7;

    // Stage Q once (raw query — reference discards q_proj)
    load_split_tile<128>(Q + (size_t)(n * S_LEN + qt * 128) * EMB + h * HDIM,
                         sm + SM_QH, sm + SM_QL, tid);
    __syncthreads();

    // ldmatrix lane addressing
    const int qa_row = qb + ((g & 1) << 3) + lr;
    const uint32_t qa_sw  = ((uint32_t)(qa_row & 7)) << 4;
    const uint32_t qa_off = (uint32_t)qa_row * 128;
    const int qa_ch = g >> 1;

    const int kb_rl = ((g >> 1) << 3) + lr;     // + 16j
    const int kb_ch = g & 1;
    const int vb_rl = ((g & 1) << 3) + lr;      // + 16j
    const int vb_ch = g >> 1;

    // Q fragments: tile-invariant, load once
    uint32_t qh[4][4], ql[4][4];
    #pragma unroll
    for (int ks = 0; ks < 4; ks++) {
        uint32_t ch = (uint32_t)(2 * ks + qa_ch) << 4;
        ldsm4(qh[ks], smb + SM_QH + qa_off + (ch ^ qa_sw));
        ldsm4(ql[ks], smb + SM_QL + qa_off + (ch ^ qa_sw));
    }

    float O[8][4];
    #pragma unroll
    for (int i = 0; i < 8; i++)
        #pragma unroll
        for (int j = 0; j < 4; j++) O[i][j] = 0.f;
    float lp0 = 0.f, lp1 = 0.f;

    const float scale = 0.044194173824159216f;   // 1/sqrt(512)
    const int qrow_l = qb + (lane >> 2);         // local q row (mask/out)

    for (int kt = 0; kt < S_LEN / BCK; kt++) {
        // stage K, V (split bf16), mask bytes
        load_split_tile<BCK>(Kp + (size_t)(n * S_LEN + kt * BCK) * EMB + h * HDIM,
                             sm + SM_KH, sm + SM_KL, tid);
        load_split_tile<BCK>(Vp + (size_t)(n * S_LEN + kt * BCK) * EMB + h * HDIM,
                             sm + SM_VH, sm + SM_VL, tid);
        {
            const int* mb = mask + ((size_t)n * S_LEN + qt * 128) * S_LEN + kt * BCK;
            char* msm = sm + SM_MSK;
            #pragma unroll
            for (int i = 0; i < 8; i++) {
                int lin = tid + (i << 8);        // 128 rows x 16 int4
                int rr = lin >> 4, c4 = lin & 15;
                int4 mv = *(const int4*)(mb + (size_t)rr * S_LEN + c4 * 4);
                uint32_t pk = (uint32_t)(mv.x & 1) | ((uint32_t)(mv.y & 1) << 8) |
                              ((uint32_t)(mv.z & 1) << 16) | ((uint32_t)(mv.w & 1) << 24);
                *(uint32_t*)(msm + rr * 72 + c4 * 4) = pk;
            }
        }
        __syncthreads();

        // 4 chunks of 16 keys: QK -> exp -> PV
        #pragma unroll
        for (int j = 0; j < 4; j++) {
            float s[8];
            #pragma unroll
            for (int i = 0; i < 8; i++) s[i] = 0.f;

            const int kbrow = 16 * j + kb_rl;
            const uint32_t kb_off = (uint32_t)kbrow * 128;
            const uint32_t kb_sw  = ((uint32_t)(kbrow & 7)) << 4;

            #pragma unroll
            for (int ks = 0; ks < 4; ks++) {
                uint32_t ch = (uint32_t)(2 * ks + kb_ch) << 4;
                uint32_t kbh[4], kbl[4];
                ldsm4(kbh, smb + SM_KH + kb_off + (ch ^ kb_sw));
                mma16816(s + 0, qh[ks], kbh + 0);
                mma16816(s + 4, qh[ks], kbh + 2);
                mma16816(s + 0, ql[ks], kbh + 0);
                mma16816(s + 4, ql[ks], kbh + 2);
                ldsm4(kbl, smb + SM_KL + kb_off + (ch ^ kb_sw));
                mma16816(s + 0, qh[ks], kbl + 0);
                mma16816(s + 4, qh[ks], kbl + 2);
            }

            // mask + exp
            const char* msm = sm + SM_MSK;
            const int cb = 16 * j + 2 * (lane & 3);
            unsigned short m00 = *(const unsigned short*)(msm + qrow_l * 72 + cb);
            unsigned short m10 = *(const unsigned short*)(msm + (qrow_l + 8) * 72 + cb);
            unsigned short m01 = *(const unsigned short*)(msm + qrow_l * 72 + cb + 8);
            unsigned short m11 = *(const unsigned short*)(msm + (qrow_l + 8) * 72 + cb + 8);

            float p[8];
            p[0] = (m00 & 255) ? __expf(s[0] * scale) : 0.f;
            p[1] = (m00 >> 8)  ? __expf(s[1] * scale) : 0.f;
            p[2] = (m10 & 255) ? __expf(s[2] * scale) : 0.f;
            p[3] = (m10 >> 8)  ? __expf(s[3] * scale) : 0.f;
            p[4] = (m01 & 255) ? __expf(s[4] * scale) : 0.f;
            p[5] = (m01 >> 8)  ? __expf(s[5] * scale) : 0.f;
            p[6] = (m11 & 255) ? __expf(s[6] * scale) : 0.f;
            p[7] = (m11 >> 8)  ? __expf(s[7] * scale) : 0.f;

            lp0 += p[0] + p[1] + p[4] + p[5];
            lp1 += p[2] + p[3] + p[6] + p[7];

            // P -> A frags (hi + residual lo)
            uint32_t ph[4], pl[4];
            #pragma unroll
            for (int i = 0; i < 4; i++) {
                float a = p[2 * i], b = p[2 * i + 1];
                ph[i] = packbf2(a, b);
                float ar = a - __bfloat162float(__float2bfloat16_rn(a));
                float br = b - __bfloat162float(__float2bfloat16_rn(b));
                pl[i] = packbf2(ar, br);
            }

            // PV over 4 d-tile pairs
            const int vbrow = 16 * j + vb_rl;
            const uint32_t vb_off = (uint32_t)vbrow * 128;
            const uint32_t vb_sw  = ((uint32_t)(vbrow & 7)) << 4;
            #pragma unroll
            for (int np = 0; np < 4; np++) {
                uint32_t ch = (uint32_t)(2 * np + vb_ch) << 4;
                uint32_t vh[4], vl[4];
                ldsm4t(vh, smb + SM_VH + vb_off + (ch ^ vb_sw));
                mma16816(O[2 * np],     ph, vh + 0);
                mma16816(O[2 * np + 1], ph, vh + 2);
                mma16816(O[2 * np],     pl, vh + 0);
                mma16816(O[2 * np + 1], pl, vh + 2);
                ldsm4t(vl, smb + SM_VL + vb_off + (ch ^ vb_sw));
                mma16816(O[2 * np],     ph, vl + 0);
                mma16816(O[2 * np + 1], ph, vl + 2);
            }
        }
        __syncthreads();   // compute done before next staging overwrite
    }

    // reduce l within quads, normalize, store
    lp0 += __shfl_xor_sync(0xffffffffu, lp0, 1);
    lp0 += __shfl_xor_sync(0xffffffffu, lp0, 2);
    lp1 += __shfl_xor_sync(0xffffffffu, lp1, 1);
    lp1 += __shfl_xor_sync(0xffffffffu, lp1, 2);
    float inv0 = 1.f / lp0, inv1 = 1.f / lp1;

    const size_t grow = (size_t)(n * S_LEN + qt * 128 + qrow_l) * EMB + h * HDIM;
    const int cb = 2 * (lane & 3);
    #pragma unroll
    for (int nt = 0; nt < 8; nt++) {
        float2 o0 = make_float2(O[nt][0] * inv0, O[nt][1] * inv0);
        float2 o1 = make_float2(O[nt][2] * inv1, O[nt][3] * inv1);
        *(float2*)(ctx + grow + nt * 8 + cb) = o0;
        *(float2*)(ctx + grow + 8 * EMB + nt * 8 + cb) = o1;
    }
}

// ---------------------------------------------------------------------------

extern "C" void kernel_launch(void* const* d_in, const int* in_sizes, int n_in,
                              void* d_out, int out_size)
{
    const float* values = (const float*)d_in[0];
    const float* keys_  = (const float*)d_in[1];
    const float* query  = (const float*)d_in[2];
    const int*   mask   = (const int*)d_in[3];
    // d_in[4] = Wq : intentionally unused (reference discards q_proj)
    const float* Wk = (const float*)d_in[5];
    const float* Wv = (const float*)d_in[6];
    const float* Wo = (const float*)d_in[7];
    const float* bo = (const float*)d_in[8];
    float* out = (float*)d_out;

    float *Kp, *Vp, *Cp;
    cudaGetSymbolAddress((void**)&Kp, g_K);
    cudaGetSymbolAddress((void**)&Vp, g_V);
    cudaGetSymbolAddress((void**)&Cp, g_C);

    const int M = NBATCH * S_LEN;  // 8192
    dim3 ggrid(M / 128, EMB / 128);

    gemm_nt<<<ggrid, 256>>>(keys_, Wk, nullptr, Kp, M);
    gemm_nt<<<ggrid, 256>>>(values, Wv, nullptr, Vp, M);

    cudaFuncSetAttribute(attn3, cudaFuncAttributeMaxDynamicSharedMemorySize,
                         SM_TOTAL);
    int nblocks = NBATCH * (S_LEN / 128) * NHEADS;  // 512, h fastest (mask L2 reuse)
    attn3<<<nblocks, 256, SM_TOTAL>>>(query, mask, Kp, Vp, Cp);

    gemm_nt<<<ggrid, 256>>>(Cp, Wo, bo, out, M);
}